// round 6
// baseline (speedup 1.0000x reference)
#include <cuda_runtime.h>
#include <cstdint>

// Problem constants
#define B_   2
#define T_   2048
#define C_   2048
#define H_   16
#define DH_  128
#define M_   (B_ * T_)   // 4096

// Scratch (device globals — allocation-free per harness rules)
__device__ float g_Q[(size_t)M_ * C_];     // tf32-rounded
__device__ float g_K[(size_t)M_ * DH_];
__device__ float g_V[(size_t)M_ * DH_];
__device__ float g_Y[(size_t)M_ * C_];
__device__ float g_Xr[(size_t)M_ * C_];
__device__ float g_Wqr[(size_t)C_ * C_];
__device__ float g_Wkr[(size_t)C_ * DH_];
__device__ float g_Wvr[(size_t)C_ * DH_];
__device__ float g_Wor[(size_t)C_ * C_];

__device__ __forceinline__ float tf32r(float x) {
    float y;
    asm("cvt.rna.tf32.f32 %0, %1;" : "=f"(y) : "f"(x));
    return y;
}

__device__ __forceinline__ uint32_t smem_u32(const void* p) {
    uint32_t a;
    asm("{ .reg .u64 t; cvta.to.shared.u64 t, %1; cvt.u32.u64 %0, t; }"
        : "=r"(a) : "l"(p));
    return a;
}

__device__ __forceinline__ void cp16(uint32_t dst, const void* src) {
    asm volatile("cp.async.cg.shared.global [%0], [%1], 16;" :: "r"(dst), "l"(src));
}
#define CP_COMMIT() asm volatile("cp.async.commit_group;" ::: "memory")
#define CP_WAIT(n)  asm volatile("cp.async.wait_group %0;" :: "n"(n) : "memory")

__device__ __forceinline__ void mma_tf32(float* d, const uint32_t* a, const uint32_t* b) {
    asm volatile(
        "mma.sync.aligned.m16n8k8.row.col.f32.tf32.tf32.f32 "
        "{%0,%1,%2,%3}, {%4,%5,%6,%7}, {%8,%9}, {%0,%1,%2,%3};"
        : "+f"(d[0]), "+f"(d[1]), "+f"(d[2]), "+f"(d[3])
        : "r"(a[0]), "r"(a[1]), "r"(a[2]), "r"(a[3]), "r"(b[0]), "r"(b[1]));
}

// ---------------------------------------------------------------------------
// Pre-round to tf32
// ---------------------------------------------------------------------------
__global__ __launch_bounds__(256) void round_tf32(
    const float4* __restrict__ in, float4* __restrict__ out, int n4)
{
    int i = blockIdx.x * 256 + threadIdx.x;
    if (i < n4) {
        float4 v = in[i];
        v.x = tf32r(v.x); v.y = tf32r(v.y); v.z = tf32r(v.z); v.w = tf32r(v.w);
        out[i] = v;
    }
}

// ---------------------------------------------------------------------------
// tf32 GEMM, BK=32, cp.async double-buffered, occupancy 2, dynamic smem.
// CTA tile 128x128, 8 warps (2x4), warp tile 64x32.
// ---------------------------------------------------------------------------
#define AS_STRIDE 36
#define BS_STRIDE 136
#define GA_ELEMS (128 * AS_STRIDE)
#define GB_ELEMS (32 * BS_STRIDE)
#define GEMM_SMEM ((2 * GA_ELEMS + 2 * GB_ELEMS) * 4)   // 71680 B

template<bool ROUND_OUT>
__device__ __forceinline__ void gemm_body(
    const float* __restrict__ A, const float* __restrict__ B,
    float* __restrict__ Cc, int Nc, int Kd)
{
    extern __shared__ float gsm[];
    float* Asf[2] = { gsm, gsm + GA_ELEMS };
    float* Bsf[2] = { gsm + 2 * GA_ELEMS, gsm + 2 * GA_ELEMS + GB_ELEMS };
    const uint32_t asb[2] = { smem_u32(Asf[0]), smem_u32(Asf[1]) };
    const uint32_t bsb[2] = { smem_u32(Bsf[0]), smem_u32(Bsf[1]) };

    const int tid    = threadIdx.x;
    const int wid    = tid >> 5;
    const int lane   = tid & 31;
    const int g      = lane >> 2;
    const int tq     = lane & 3;
    const int warp_m = wid & 1;
    const int warp_n = wid >> 1;
    const int rowBase = blockIdx.y * 128;
    const int colBase = blockIdx.x * 128;

    float acc[4][4][4];
    #pragma unroll
    for (int mi = 0; mi < 4; mi++)
        #pragma unroll
        for (int ni = 0; ni < 4; ni++)
            #pragma unroll
            for (int r = 0; r < 4; r++) acc[mi][ni][r] = 0.0f;

    const int nK = Kd >> 5;   // BK=32 chunks

    auto issue = [&](int kc, int s) {
        // A tile: 128 rows x 32 floats = 1024 x 16B
        #pragma unroll
        for (int j = 0; j < 4; j++) {
            int op = tid + 256 * j;
            int r = op >> 3, sg = op & 7;
            cp16(asb[s] + (uint32_t)(r * AS_STRIDE + sg * 4) * 4,
                 A + (size_t)(rowBase + r) * Kd + kc * 32 + sg * 4);
        }
        // B tile: 32 rows x 128 floats = 1024 x 16B
        #pragma unroll
        for (int j = 0; j < 4; j++) {
            int op = tid + 256 * j;
            int r = op >> 5, sg = op & 31;
            cp16(bsb[s] + (uint32_t)(r * BS_STRIDE + sg * 4) * 4,
                 B + (size_t)(kc * 32 + r) * Nc + colBase + sg * 4);
        }
    };

    issue(0, 0);
    CP_COMMIT();

    for (int kc = 0; kc < nK; kc++) {
        const int s = kc & 1;
        if (kc + 1 < nK) {
            issue(kc + 1, s ^ 1);
            CP_COMMIT();
            CP_WAIT(1);
        } else {
            CP_WAIT(0);
        }
        __syncthreads();

        #pragma unroll
        for (int ks = 0; ks < 4; ks++) {
            uint32_t af[4][4], bf[4][2];
            #pragma unroll
            for (int mi = 0; mi < 4; mi++) {
                int m0 = warp_m * 64 + mi * 16 + g;
                int kk = ks * 8 + tq;
                af[mi][0] = __float_as_uint(Asf[s][m0 * AS_STRIDE + kk]);
                af[mi][1] = __float_as_uint(Asf[s][(m0 + 8) * AS_STRIDE + kk]);
                af[mi][2] = __float_as_uint(Asf[s][m0 * AS_STRIDE + kk + 4]);
                af[mi][3] = __float_as_uint(Asf[s][(m0 + 8) * AS_STRIDE + kk + 4]);
            }
            #pragma unroll
            for (int ni = 0; ni < 4; ni++) {
                int n0 = warp_n * 32 + ni * 8 + g;
                int kk = ks * 8 + tq;
                bf[ni][0] = __float_as_uint(Bsf[s][kk * BS_STRIDE + n0]);
                bf[ni][1] = __float_as_uint(Bsf[s][(kk + 4) * BS_STRIDE + n0]);
            }
            #pragma unroll
            for (int mi = 0; mi < 4; mi++)
                #pragma unroll
                for (int ni = 0; ni < 4; ni++)
                    mma_tf32(acc[mi][ni], af[mi], bf[ni]);
        }
        __syncthreads();
    }

    #pragma unroll
    for (int mi = 0; mi < 4; mi++) {
        int row = rowBase + warp_m * 64 + mi * 16 + g;
        #pragma unroll
        for (int ni = 0; ni < 4; ni++) {
            int col = colBase + warp_n * 32 + ni * 8 + tq * 2;
            float v0 = acc[mi][ni][0], v1 = acc[mi][ni][1];
            float v2 = acc[mi][ni][2], v3 = acc[mi][ni][3];
            if (ROUND_OUT) { v0 = tf32r(v0); v1 = tf32r(v1); v2 = tf32r(v2); v3 = tf32r(v3); }
            *reinterpret_cast<float2*>(&Cc[(size_t)row * Nc + col])       = make_float2(v0, v1);
            *reinterpret_cast<float2*>(&Cc[(size_t)(row + 8) * Nc + col]) = make_float2(v2, v3);
        }
    }
}

template<bool ROUND_OUT>
__global__ __launch_bounds__(256, 2) void gemm_async(
    const float* __restrict__ A, const float* __restrict__ B,
    float* __restrict__ Cc, int Nc, int Kd)
{
    gemm_body<ROUND_OUT>(A, B, Cc, Nc, Kd);
}

__global__ __launch_bounds__(256, 2) void gemm_kv(
    const float* __restrict__ A,
    const float* __restrict__ Bk, const float* __restrict__ Bv,
    float* __restrict__ Ck, float* __restrict__ Cv, int Nc, int Kd)
{
    const float* Bp = blockIdx.z ? Bv : Bk;
    float*       Cp = blockIdx.z ? Cv : Ck;
    gemm_body<true>(A, Bp, Cp, Nc, Kd);
}

// ---------------------------------------------------------------------------
// Tensor-core flash attention, 128 threads (4 warps x 16 rows), 64 queries/CTA,
// occupancy 2. Single K/V buffers with temporal cp.async pipelining:
//   K(it+1) prefetched behind O(it), V(it+1) behind S(it+1).
// Grid: (T/64, H, B).
// ---------------------------------------------------------------------------
#define KSTR 132
#define VSTR 136
#define PSTR 68
#define F_OFF_V (64 * KSTR)
#define F_OFF_P (64 * KSTR + 64 * VSTR)
#define FL_SMEM ((F_OFF_P + 4 * 16 * PSTR) * 4)   // 86016 B

__global__ __launch_bounds__(128, 2) void flash_mqa_mma(
    const float* __restrict__ Q, const float* __restrict__ K,
    const float* __restrict__ V, float* __restrict__ Y)
{
    extern __shared__ float fsm[];
    const uint32_t sb = smem_u32(fsm);

    const int tid  = threadIdx.x;
    const int wid  = tid >> 5;          // 0..3
    const int lane = tid & 31;
    const int g    = lane >> 2;
    const int tq   = lane & 3;
    const int q0   = blockIdx.x * 64;
    const int h    = blockIdx.y;
    const int b    = blockIdx.z;
    const int m0   = wid * 16;
    const float scale = 0.08838834764831845f;   // 128^-0.5

    // ---- Stage Q (64x128) into the K region, grab fragments
    const float* Qb = Q + ((size_t)b * T_ + q0) * C_ + h * DH_;
    #pragma unroll
    for (int j = 0; j < 16; j++) {
        int op = tid + 128 * j;        // 0..2047
        int r = op >> 5, sg = op & 31;
        cp16(sb + (uint32_t)(r * KSTR + sg * 4) * 4, Qb + (size_t)r * C_ + sg * 4);
    }
    CP_COMMIT(); CP_WAIT(0);
    __syncthreads();

    uint32_t qf[16][4];
    #pragma unroll
    for (int kk = 0; kk < 16; kk++) {
        qf[kk][0] = __float_as_uint(fsm[(m0 + g)     * KSTR + 8 * kk + tq]);
        qf[kk][1] = __float_as_uint(fsm[(m0 + g + 8) * KSTR + 8 * kk + tq]);
        qf[kk][2] = __float_as_uint(fsm[(m0 + g)     * KSTR + 8 * kk + tq + 4]);
        qf[kk][3] = __float_as_uint(fsm[(m0 + g + 8) * KSTR + 8 * kk + tq + 4]);
    }
    __syncthreads();

    float oacc[16][4];
    #pragma unroll
    for (int nf = 0; nf < 16; nf++)
        #pragma unroll
        for (int r = 0; r < 4; r++) oacc[nf][r] = 0.0f;
    float mrow0 = -1e30f, mrow1 = -1e30f, lrow0 = 0.0f, lrow1 = 0.0f;

    const float* Kb = K + (size_t)b * T_ * DH_;
    const float* Vb = V + (size_t)b * T_ * DH_;
    float* Psw = fsm + F_OFF_P + wid * 16 * PSTR;

    auto issue_K = [&](int s0t) {
        const float* Kt = Kb + (size_t)s0t * DH_;
        #pragma unroll
        for (int j = 0; j < 16; j++) {
            int op = tid + 128 * j;
            int r = op >> 5, sg = op & 31;
            cp16(sb + (uint32_t)(r * KSTR + sg * 4) * 4, Kt + (size_t)r * DH_ + sg * 4);
        }
    };
    auto issue_V = [&](int s0t) {
        const float* Vt = Vb + (size_t)s0t * DH_;
        #pragma unroll
        for (int j = 0; j < 16; j++) {
            int op = tid + 128 * j;
            int r = op >> 5, sg = op & 31;
            cp16(sb + (uint32_t)(F_OFF_V + r * VSTR + sg * 4) * 4, Vt + (size_t)r * DH_ + sg * 4);
        }
    };

    issue_K(0); CP_COMMIT();
    issue_V(0); CP_COMMIT();

    const int nTiles = T_ / 64;   // 32
    for (int it = 0; it < nTiles; it++) {
        // ---- wait K(it): all but newest group (V(it)) complete
        CP_WAIT(1);
        __syncthreads();

        const float* Ks = fsm;
        const float* Vs = fsm + F_OFF_V;

        // ---- S = Q @ K^T  (16 rows x 64 keys per warp)
        float sacc[8][4];
        #pragma unroll
        for (int nf = 0; nf < 8; nf++)
            #pragma unroll
            for (int r = 0; r < 4; r++) sacc[nf][r] = 0.0f;

        #pragma unroll
        for (int kk = 0; kk < 16; kk++) {
            #pragma unroll
            for (int nf = 0; nf < 8; nf++) {
                uint32_t bfr[2];
                bfr[0] = __float_as_uint(Ks[(nf * 8 + g) * KSTR + 8 * kk + tq]);
                bfr[1] = __float_as_uint(Ks[(nf * 8 + g) * KSTR + 8 * kk + tq + 4]);
                mma_tf32(sacc[nf], qf[kk], bfr);
            }
        }
        #pragma unroll
        for (int nf = 0; nf < 8; nf++) {
            sacc[nf][0] *= scale; sacc[nf][1] *= scale;
            sacc[nf][2] *= scale; sacc[nf][3] *= scale;
        }

        // ---- online softmax
        float mx0 = -1e30f, mx1 = -1e30f;
        #pragma unroll
        for (int nf = 0; nf < 8; nf++) {
            mx0 = fmaxf(mx0, fmaxf(sacc[nf][0], sacc[nf][1]));
            mx1 = fmaxf(mx1, fmaxf(sacc[nf][2], sacc[nf][3]));
        }
        mx0 = fmaxf(mx0, __shfl_xor_sync(0xffffffffu, mx0, 1));
        mx0 = fmaxf(mx0, __shfl_xor_sync(0xffffffffu, mx0, 2));
        mx1 = fmaxf(mx1, __shfl_xor_sync(0xffffffffu, mx1, 1));
        mx1 = fmaxf(mx1, __shfl_xor_sync(0xffffffffu, mx1, 2));
        float mn0 = fmaxf(mrow0, mx0), mn1 = fmaxf(mrow1, mx1);
        float a0 = __expf(mrow0 - mn0), a1 = __expf(mrow1 - mn1);
        float rs0 = 0.0f, rs1 = 0.0f;
        #pragma unroll
        for (int nf = 0; nf < 8; nf++) {
            sacc[nf][0] = __expf(sacc[nf][0] - mn0);
            sacc[nf][1] = __expf(sacc[nf][1] - mn0);
            sacc[nf][2] = __expf(sacc[nf][2] - mn1);
            sacc[nf][3] = __expf(sacc[nf][3] - mn1);
            rs0 += sacc[nf][0] + sacc[nf][1];
            rs1 += sacc[nf][2] + sacc[nf][3];
        }
        rs0 += __shfl_xor_sync(0xffffffffu, rs0, 1);
        rs0 += __shfl_xor_sync(0xffffffffu, rs0, 2);
        rs1 += __shfl_xor_sync(0xffffffffu, rs1, 1);
        rs1 += __shfl_xor_sync(0xffffffffu, rs1, 2);
        lrow0 = lrow0 * a0 + rs0;  mrow0 = mn0;
        lrow1 = lrow1 * a1 + rs1;  mrow1 = mn1;
        #pragma unroll
        for (int nf = 0; nf < 16; nf++) {
            oacc[nf][0] *= a0; oacc[nf][1] *= a0;
            oacc[nf][2] *= a1; oacc[nf][3] *= a1;
        }
        // publish P (tf32)
        #pragma unroll
        for (int nf = 0; nf < 8; nf++) {
            *reinterpret_cast<float2*>(&Psw[g * PSTR + nf * 8 + tq * 2]) =
                make_float2(tf32r(sacc[nf][0]), tf32r(sacc[nf][1]));
            *reinterpret_cast<float2*>(&Psw[(g + 8) * PSTR + nf * 8 + tq * 2]) =
                make_float2(tf32r(sacc[nf][2]), tf32r(sacc[nf][3]));
        }

        // ---- all warps finished reading Ks -> prefetch K(it+1) behind O-phase
        __syncthreads();
        if (it + 1 < nTiles) { issue_K((it + 1) * 64); CP_COMMIT(); }

        // ---- wait V(it)
        if (it + 1 < nTiles) { CP_WAIT(1); } else { CP_WAIT(0); }
        __syncthreads();

        // ---- O += P @ V
        #pragma unroll
        for (int kk = 0; kk < 8; kk++) {
            uint32_t pf[4];
            pf[0] = __float_as_uint(Psw[g       * PSTR + 8 * kk + tq]);
            pf[1] = __float_as_uint(Psw[(g + 8) * PSTR + 8 * kk + tq]);
            pf[2] = __float_as_uint(Psw[g       * PSTR + 8 * kk + tq + 4]);
            pf[3] = __float_as_uint(Psw[(g + 8) * PSTR + 8 * kk + tq + 4]);
            #pragma unroll
            for (int nf = 0; nf < 16; nf++) {
                uint32_t bfr[2];
                bfr[0] = __float_as_uint(Vs[(8 * kk + tq)     * VSTR + nf * 8 + g]);
                bfr[1] = __float_as_uint(Vs[(8 * kk + tq + 4) * VSTR + nf * 8 + g]);
                mma_tf32(oacc[nf], pf, bfr);
            }
        }

        // ---- Vs reads done -> prefetch V(it+1) behind next S-phase
        __syncthreads();
        if (it + 1 < nTiles) { issue_V((it + 1) * 64); CP_COMMIT(); }
    }

    // ---- epilogue: normalize, round (feeds O-proj), write Y
    float i0 = 1.0f / lrow0, i1 = 1.0f / lrow1;
    size_t row0 = (size_t)b * T_ + q0 + m0 + g;
    size_t row1 = row0 + 8;
    #pragma unroll
    for (int nf = 0; nf < 16; nf++) {
        int col = h * DH_ + nf * 8 + tq * 2;
        *reinterpret_cast<float2*>(&Y[row0 * C_ + col]) =
            make_float2(tf32r(oacc[nf][0] * i0), tf32r(oacc[nf][1] * i0));
        *reinterpret_cast<float2*>(&Y[row1 * C_ + col]) =
            make_float2(tf32r(oacc[nf][2] * i1), tf32r(oacc[nf][3] * i1));
    }
}

// ---------------------------------------------------------------------------
// Launch
// ---------------------------------------------------------------------------
extern "C" void kernel_launch(void* const* d_in, const int* in_sizes, int n_in,
                              void* d_out, int out_size)
{
    const float* x  = (const float*)d_in[0];
    const float* Wq = (const float*)d_in[1];
    const float* Wk = (const float*)d_in[2];
    const float* Wv = (const float*)d_in[3];
    const float* Wo = (const float*)d_in[4];
    float* out = (float*)d_out;

    float *Qp, *Kp, *Vp, *Yp, *Xr, *Wqr, *Wkr, *Wvr, *Wor;
    cudaGetSymbolAddress((void**)&Qp,  g_Q);
    cudaGetSymbolAddress((void**)&Kp,  g_K);
    cudaGetSymbolAddress((void**)&Vp,  g_V);
    cudaGetSymbolAddress((void**)&Yp,  g_Y);
    cudaGetSymbolAddress((void**)&Xr,  g_Xr);
    cudaGetSymbolAddress((void**)&Wqr, g_Wqr);
    cudaGetSymbolAddress((void**)&Wkr, g_Wkr);
    cudaGetSymbolAddress((void**)&Wvr, g_Wvr);
    cudaGetSymbolAddress((void**)&Wor, g_Wor);

    cudaFuncSetAttribute(gemm_async<true>,  cudaFuncAttributeMaxDynamicSharedMemorySize, GEMM_SMEM);
    cudaFuncSetAttribute(gemm_async<false>, cudaFuncAttributeMaxDynamicSharedMemorySize, GEMM_SMEM);
    cudaFuncSetAttribute(gemm_kv,           cudaFuncAttributeMaxDynamicSharedMemorySize, GEMM_SMEM);
    cudaFuncSetAttribute(flash_mqa_mma,     cudaFuncAttributeMaxDynamicSharedMemorySize, FL_SMEM);

    // Pre-round inputs to tf32
    round_tf32<<<(M_ * C_ / 4) / 256, 256>>>((const float4*)x,  (float4*)Xr,  M_ * C_ / 4);
    round_tf32<<<(C_ * C_ / 4) / 256, 256>>>((const float4*)Wq, (float4*)Wqr, C_ * C_ / 4);
    round_tf32<<<(C_ * DH_ / 4) / 256, 256>>>((const float4*)Wk, (float4*)Wkr, C_ * DH_ / 4);
    round_tf32<<<(C_ * DH_ / 4) / 256, 256>>>((const float4*)Wv, (float4*)Wvr, C_ * DH_ / 4);
    round_tf32<<<(C_ * C_ / 4) / 256, 256>>>((const float4*)Wo, (float4*)Wor, C_ * C_ / 4);

    // 1) Q = xr @ Wqr (rounded output)
    gemm_async<true><<<dim3(C_ / 128, M_ / 128), 256, GEMM_SMEM>>>(Xr, Wqr, Qp, C_, C_);
    // 2+3) K,V projections fused (rounded outputs)
    gemm_kv<<<dim3(1, M_ / 128, 2), 256, GEMM_SMEM>>>(Xr, Wkr, Wvr, Kp, Vp, DH_, C_);
    // 4) Flash MQA attention (64 queries/CTA, occupancy 2)
    flash_mqa_mma<<<dim3(T_ / 64, H_, B_), 128, FL_SMEM>>>(Qp, Kp, Vp, Yp);
    // 5) out = Y @ Wor
    gemm_async<false><<<dim3(C_ / 128, M_ / 128), 256, GEMM_SMEM>>>(Yp, Wor, out, C_, C_);
}

// round 7
// speedup vs baseline: 1.1224x; 1.1224x over previous
#include <cuda_runtime.h>
#include <cstdint>

// Problem constants
#define B_   2
#define T_   2048
#define C_   2048
#define H_   16
#define DH_  128
#define M_   (B_ * T_)   // 4096

// Scratch (device globals — allocation-free per harness rules)
__device__ float g_Q[(size_t)M_ * C_];     // tf32-rounded
__device__ float g_K[(size_t)M_ * DH_];
__device__ float g_V[(size_t)M_ * DH_];
__device__ float g_Y[(size_t)M_ * C_];
__device__ float g_Xr[(size_t)M_ * C_];
__device__ float g_Wqr[(size_t)C_ * C_];
__device__ float g_Wkr[(size_t)C_ * DH_];
__device__ float g_Wvr[(size_t)C_ * DH_];
__device__ float g_Wor[(size_t)C_ * C_];

__device__ __forceinline__ float tf32r(float x) {
    float y;
    asm("cvt.rna.tf32.f32 %0, %1;" : "=f"(y) : "f"(x));
    return y;
}

__device__ __forceinline__ uint32_t smem_u32(const void* p) {
    uint32_t a;
    asm("{ .reg .u64 t; cvta.to.shared.u64 t, %1; cvt.u32.u64 %0, t; }"
        : "=r"(a) : "l"(p));
    return a;
}

__device__ __forceinline__ void cp16(uint32_t dst, const void* src) {
    asm volatile("cp.async.cg.shared.global [%0], [%1], 16;" :: "r"(dst), "l"(src));
}
#define CP_COMMIT() asm volatile("cp.async.commit_group;" ::: "memory")
#define CP_WAIT(n)  asm volatile("cp.async.wait_group %0;" :: "n"(n) : "memory")

__device__ __forceinline__ void mma_tf32(float* d, const uint32_t* a, const uint32_t* b) {
    asm volatile(
        "mma.sync.aligned.m16n8k8.row.col.f32.tf32.tf32.f32 "
        "{%0,%1,%2,%3}, {%4,%5,%6,%7}, {%8,%9}, {%0,%1,%2,%3};"
        : "+f"(d[0]), "+f"(d[1]), "+f"(d[2]), "+f"(d[3])
        : "r"(a[0]), "r"(a[1]), "r"(a[2]), "r"(a[3]), "r"(b[0]), "r"(b[1]));
}

// ---------------------------------------------------------------------------
// Pre-round to tf32
// ---------------------------------------------------------------------------
__global__ __launch_bounds__(256) void round_tf32(
    const float4* __restrict__ in, float4* __restrict__ out, int n4)
{
    int i = blockIdx.x * 256 + threadIdx.x;
    if (i < n4) {
        float4 v = in[i];
        v.x = tf32r(v.x); v.y = tf32r(v.y); v.z = tf32r(v.z); v.w = tf32r(v.w);
        out[i] = v;
    }
}

// ---------------------------------------------------------------------------
// tf32 GEMM, BK=16, 3-stage cp.async pipeline, occupancy 2.
// CTA tile 128x128, 8 warps (2x4), warp tile 64x32. One sync per chunk.
// ---------------------------------------------------------------------------
#define AS_STRIDE 20
#define BS_STRIDE 136
#define GA_ELEMS (128 * AS_STRIDE)
#define GB_ELEMS (16 * BS_STRIDE)
#define G_STAGE  (GA_ELEMS + GB_ELEMS)          // 4736 floats
#define GEMM_SMEM (3 * G_STAGE * 4)             // 56832 B

template<bool ROUND_OUT>
__device__ __forceinline__ void gemm_body(
    const float* __restrict__ A, const float* __restrict__ B,
    float* __restrict__ Cc, int Nc, int Kd)
{
    extern __shared__ float gsm[];

    const int tid    = threadIdx.x;
    const int wid    = tid >> 5;
    const int lane   = tid & 31;
    const int g      = lane >> 2;
    const int tq     = lane & 3;
    const int warp_m = wid & 1;
    const int warp_n = wid >> 1;
    const int rowBase = blockIdx.y * 128;
    const int colBase = blockIdx.x * 128;

    float acc[4][4][4];
    #pragma unroll
    for (int mi = 0; mi < 4; mi++)
        #pragma unroll
        for (int ni = 0; ni < 4; ni++)
            #pragma unroll
            for (int r = 0; r < 4; r++) acc[mi][ni][r] = 0.0f;

    const int nK = Kd >> 4;

    auto issue = [&](int kc, int s) {
        uint32_t ab = smem_u32(gsm + s * G_STAGE);
        uint32_t bb = ab + GA_ELEMS * 4;
        // A tile: 128 rows x 16 floats = 512 x 16B
        #pragma unroll
        for (int j = 0; j < 2; j++) {
            int op = tid + 256 * j;
            int r = op >> 2, sg = op & 3;
            cp16(ab + (uint32_t)(r * AS_STRIDE + sg * 4) * 4,
                 A + (size_t)(rowBase + r) * Kd + kc * 16 + sg * 4);
        }
        // B tile: 16 rows x 128 floats = 512 x 16B
        #pragma unroll
        for (int j = 0; j < 2; j++) {
            int op = tid + 256 * j;
            int r = op >> 5, sg = op & 31;
            cp16(bb + (uint32_t)(r * BS_STRIDE + sg * 4) * 4,
                 B + (size_t)(kc * 16 + r) * Nc + colBase + sg * 4);
        }
    };

    issue(0, 0); CP_COMMIT();
    issue(1, 1); CP_COMMIT();

    int s = 0;
    for (int kc = 0; kc < nK; kc++) {
        if (kc + 1 < nK) { CP_WAIT(1); } else { CP_WAIT(0); }
        __syncthreads();
        if (kc + 2 < nK) { issue(kc + 2, (kc + 2) % 3); CP_COMMIT(); }

        const float* Asf = gsm + s * G_STAGE;
        const float* Bsf = Asf + GA_ELEMS;

        #pragma unroll
        for (int ks = 0; ks < 2; ks++) {
            uint32_t af[4][4], bf[4][2];
            #pragma unroll
            for (int mi = 0; mi < 4; mi++) {
                int m0 = warp_m * 64 + mi * 16 + g;
                int kk = ks * 8 + tq;
                af[mi][0] = __float_as_uint(Asf[m0 * AS_STRIDE + kk]);
                af[mi][1] = __float_as_uint(Asf[(m0 + 8) * AS_STRIDE + kk]);
                af[mi][2] = __float_as_uint(Asf[m0 * AS_STRIDE + kk + 4]);
                af[mi][3] = __float_as_uint(Asf[(m0 + 8) * AS_STRIDE + kk + 4]);
            }
            #pragma unroll
            for (int ni = 0; ni < 4; ni++) {
                int n0 = warp_n * 32 + ni * 8 + g;
                int kk = ks * 8 + tq;
                bf[ni][0] = __float_as_uint(Bsf[kk * BS_STRIDE + n0]);
                bf[ni][1] = __float_as_uint(Bsf[(kk + 4) * BS_STRIDE + n0]);
            }
            #pragma unroll
            for (int mi = 0; mi < 4; mi++)
                #pragma unroll
                for (int ni = 0; ni < 4; ni++)
                    mma_tf32(acc[mi][ni], af[mi], bf[ni]);
        }
        s = (s + 1 == 3) ? 0 : s + 1;
    }

    #pragma unroll
    for (int mi = 0; mi < 4; mi++) {
        int row = rowBase + warp_m * 64 + mi * 16 + g;
        #pragma unroll
        for (int ni = 0; ni < 4; ni++) {
            int col = colBase + warp_n * 32 + ni * 8 + tq * 2;
            float v0 = acc[mi][ni][0], v1 = acc[mi][ni][1];
            float v2 = acc[mi][ni][2], v3 = acc[mi][ni][3];
            if (ROUND_OUT) { v0 = tf32r(v0); v1 = tf32r(v1); v2 = tf32r(v2); v3 = tf32r(v3); }
            *reinterpret_cast<float2*>(&Cc[(size_t)row * Nc + col])       = make_float2(v0, v1);
            *reinterpret_cast<float2*>(&Cc[(size_t)(row + 8) * Nc + col]) = make_float2(v2, v3);
        }
    }
}

template<bool ROUND_OUT>
__global__ __launch_bounds__(256, 2) void gemm_async(
    const float* __restrict__ A, const float* __restrict__ B,
    float* __restrict__ Cc, int Nc, int Kd)
{
    gemm_body<ROUND_OUT>(A, B, Cc, Nc, Kd);
}

__global__ __launch_bounds__(256, 2) void gemm_kv(
    const float* __restrict__ A,
    const float* __restrict__ Bk, const float* __restrict__ Bv,
    float* __restrict__ Ck, float* __restrict__ Cv, int Nc, int Kd)
{
    const float* Bp = blockIdx.z ? Bv : Bk;
    float*       Cp = blockIdx.z ? Cv : Ck;
    gemm_body<true>(A, Bp, Cp, Nc, Kd);
}

// ---------------------------------------------------------------------------
// Tensor-core flash attention: 256 threads (8 warps x 16 rows), 128 queries/CTA,
// 128-KEY tiles, single K/V buffers with temporal cp.async pipelining:
// K(it+1) behind O-phase, V(it+1) behind S-phase. Grid: (T/128, H, B).
// ---------------------------------------------------------------------------
#define KSTR 132
#define VSTR 136
#define PSTR 132
#define F_OFF_V (128 * KSTR)
#define F_OFF_P (128 * KSTR + 128 * VSTR)
#define FL_SMEM ((F_OFF_P + 8 * 16 * PSTR) * 4)   // 204800 B

__global__ __launch_bounds__(256, 1) void flash_mqa_mma(
    const float* __restrict__ Q, const float* __restrict__ K,
    const float* __restrict__ V, float* __restrict__ Y)
{
    extern __shared__ float fsm[];
    const uint32_t sb = smem_u32(fsm);

    const int tid  = threadIdx.x;
    const int wid  = tid >> 5;
    const int lane = tid & 31;
    const int g    = lane >> 2;
    const int tq   = lane & 3;
    const int q0   = blockIdx.x * 128;
    const int h    = blockIdx.y;
    const int b    = blockIdx.z;
    const int m0   = wid * 16;
    const float scale = 0.08838834764831845f;   // 128^-0.5

    // ---- Stage Q (128x128) into K region, grab fragments
    const float* Qb = Q + ((size_t)b * T_ + q0) * C_ + h * DH_;
    #pragma unroll
    for (int j = 0; j < 16; j++) {
        int op = tid + 256 * j;       // 0..4095
        int r = op >> 5, sg = op & 31;
        cp16(sb + (uint32_t)(r * KSTR + sg * 4) * 4, Qb + (size_t)r * C_ + sg * 4);
    }
    CP_COMMIT(); CP_WAIT(0);
    __syncthreads();

    uint32_t qf[16][4];
    #pragma unroll
    for (int kk = 0; kk < 16; kk++) {
        qf[kk][0] = __float_as_uint(fsm[(m0 + g)     * KSTR + 8 * kk + tq]);
        qf[kk][1] = __float_as_uint(fsm[(m0 + g + 8) * KSTR + 8 * kk + tq]);
        qf[kk][2] = __float_as_uint(fsm[(m0 + g)     * KSTR + 8 * kk + tq + 4]);
        qf[kk][3] = __float_as_uint(fsm[(m0 + g + 8) * KSTR + 8 * kk + tq + 4]);
    }
    __syncthreads();

    float oacc[16][4];
    #pragma unroll
    for (int nf = 0; nf < 16; nf++)
        #pragma unroll
        for (int r = 0; r < 4; r++) oacc[nf][r] = 0.0f;
    float mrow0 = -1e30f, mrow1 = -1e30f, lrow0 = 0.0f, lrow1 = 0.0f;

    const float* Kb = K + (size_t)b * T_ * DH_;
    const float* Vb = V + (size_t)b * T_ * DH_;
    float* Psw = fsm + F_OFF_P + wid * 16 * PSTR;

    auto issue_K = [&](int s0t) {
        const float* Kt = Kb + (size_t)s0t * DH_;
        #pragma unroll
        for (int j = 0; j < 16; j++) {
            int op = tid + 256 * j;   // 0..4095 (128 rows x 32 f4)
            int r = op >> 5, sg = op & 31;
            cp16(sb + (uint32_t)(r * KSTR + sg * 4) * 4, Kt + (size_t)r * DH_ + sg * 4);
        }
    };
    auto issue_V = [&](int s0t) {
        const float* Vt = Vb + (size_t)s0t * DH_;
        #pragma unroll
        for (int j = 0; j < 16; j++) {
            int op = tid + 256 * j;
            int r = op >> 5, sg = op & 31;
            cp16(sb + (uint32_t)(F_OFF_V + r * VSTR + sg * 4) * 4, Vt + (size_t)r * DH_ + sg * 4);
        }
    };

    issue_K(0); CP_COMMIT();
    issue_V(0); CP_COMMIT();

    const int nTiles = T_ / 128;   // 16
    for (int it = 0; it < nTiles; it++) {
        // ---- wait K(it) (V(it) may still be in flight)
        CP_WAIT(1);
        __syncthreads();

        const float* Ks = fsm;
        const float* Vs = fsm + F_OFF_V;

        // ---- S = Q @ K^T  (16 rows x 128 keys per warp)
        float sacc[16][4];
        #pragma unroll
        for (int nf = 0; nf < 16; nf++)
            #pragma unroll
            for (int r = 0; r < 4; r++) sacc[nf][r] = 0.0f;

        #pragma unroll
        for (int kk = 0; kk < 16; kk++) {
            #pragma unroll
            for (int nf = 0; nf < 16; nf++) {
                uint32_t bfr[2];
                bfr[0] = __float_as_uint(Ks[(nf * 8 + g) * KSTR + 8 * kk + tq]);
                bfr[1] = __float_as_uint(Ks[(nf * 8 + g) * KSTR + 8 * kk + tq + 4]);
                mma_tf32(sacc[nf], qf[kk], bfr);
            }
        }
        #pragma unroll
        for (int nf = 0; nf < 16; nf++) {
            sacc[nf][0] *= scale; sacc[nf][1] *= scale;
            sacc[nf][2] *= scale; sacc[nf][3] *= scale;
        }

        // ---- online softmax (one pass per 128 keys)
        float mx0 = -1e30f, mx1 = -1e30f;
        #pragma unroll
        for (int nf = 0; nf < 16; nf++) {
            mx0 = fmaxf(mx0, fmaxf(sacc[nf][0], sacc[nf][1]));
            mx1 = fmaxf(mx1, fmaxf(sacc[nf][2], sacc[nf][3]));
        }
        mx0 = fmaxf(mx0, __shfl_xor_sync(0xffffffffu, mx0, 1));
        mx0 = fmaxf(mx0, __shfl_xor_sync(0xffffffffu, mx0, 2));
        mx1 = fmaxf(mx1, __shfl_xor_sync(0xffffffffu, mx1, 1));
        mx1 = fmaxf(mx1, __shfl_xor_sync(0xffffffffu, mx1, 2));
        float mn0 = fmaxf(mrow0, mx0), mn1 = fmaxf(mrow1, mx1);
        float a0 = __expf(mrow0 - mn0), a1 = __expf(mrow1 - mn1);
        float rs0 = 0.0f, rs1 = 0.0f;
        #pragma unroll
        for (int nf = 0; nf < 16; nf++) {
            sacc[nf][0] = __expf(sacc[nf][0] - mn0);
            sacc[nf][1] = __expf(sacc[nf][1] - mn0);
            sacc[nf][2] = __expf(sacc[nf][2] - mn1);
            sacc[nf][3] = __expf(sacc[nf][3] - mn1);
            rs0 += sacc[nf][0] + sacc[nf][1];
            rs1 += sacc[nf][2] + sacc[nf][3];
        }
        rs0 += __shfl_xor_sync(0xffffffffu, rs0, 1);
        rs0 += __shfl_xor_sync(0xffffffffu, rs0, 2);
        rs1 += __shfl_xor_sync(0xffffffffu, rs1, 1);
        rs1 += __shfl_xor_sync(0xffffffffu, rs1, 2);
        lrow0 = lrow0 * a0 + rs0;  mrow0 = mn0;
        lrow1 = lrow1 * a1 + rs1;  mrow1 = mn1;
        #pragma unroll
        for (int nf = 0; nf < 16; nf++) {
            oacc[nf][0] *= a0; oacc[nf][1] *= a0;
            oacc[nf][2] *= a1; oacc[nf][3] *= a1;
        }
        // publish P (tf32)
        #pragma unroll
        for (int nf = 0; nf < 16; nf++) {
            *reinterpret_cast<float2*>(&Psw[g * PSTR + nf * 8 + tq * 2]) =
                make_float2(tf32r(sacc[nf][0]), tf32r(sacc[nf][1]));
            *reinterpret_cast<float2*>(&Psw[(g + 8) * PSTR + nf * 8 + tq * 2]) =
                make_float2(tf32r(sacc[nf][2]), tf32r(sacc[nf][3]));
        }

        // ---- Ks reads done -> prefetch K(it+1) behind O-phase
        __syncthreads();
        if (it + 1 < nTiles) { issue_K((it + 1) * 128); CP_COMMIT(); }

        // ---- wait V(it)
        if (it + 1 < nTiles) { CP_WAIT(1); } else { CP_WAIT(0); }
        __syncthreads();

        // ---- O += P @ V  (k = 128 keys)
        #pragma unroll
        for (int kk = 0; kk < 16; kk++) {
            uint32_t pf[4];
            pf[0] = __float_as_uint(Psw[g       * PSTR + 8 * kk + tq]);
            pf[1] = __float_as_uint(Psw[(g + 8) * PSTR + 8 * kk + tq]);
            pf[2] = __float_as_uint(Psw[g       * PSTR + 8 * kk + tq + 4]);
            pf[3] = __float_as_uint(Psw[(g + 8) * PSTR + 8 * kk + tq + 4]);
            #pragma unroll
            for (int nf = 0; nf < 16; nf++) {
                uint32_t bfr[2];
                bfr[0] = __float_as_uint(Vs[(8 * kk + tq)     * VSTR + nf * 8 + g]);
                bfr[1] = __float_as_uint(Vs[(8 * kk + tq + 4) * VSTR + nf * 8 + g]);
                mma_tf32(oacc[nf], pf, bfr);
            }
        }

        // ---- Vs reads done -> prefetch V(it+1) behind next S-phase
        __syncthreads();
        if (it + 1 < nTiles) { issue_V((it + 1) * 128); CP_COMMIT(); }
    }

    // ---- epilogue: normalize, round (feeds O-proj), write Y
    float i0 = 1.0f / lrow0, i1 = 1.0f / lrow1;
    size_t row0 = (size_t)b * T_ + q0 + m0 + g;
    size_t row1 = row0 + 8;
    #pragma unroll
    for (int nf = 0; nf < 16; nf++) {
        int col = h * DH_ + nf * 8 + tq * 2;
        *reinterpret_cast<float2*>(&Y[row0 * C_ + col]) =
            make_float2(tf32r(oacc[nf][0] * i0), tf32r(oacc[nf][1] * i0));
        *reinterpret_cast<float2*>(&Y[row1 * C_ + col]) =
            make_float2(tf32r(oacc[nf][2] * i1), tf32r(oacc[nf][3] * i1));
    }
}

// ---------------------------------------------------------------------------
// Launch
// ---------------------------------------------------------------------------
extern "C" void kernel_launch(void* const* d_in, const int* in_sizes, int n_in,
                              void* d_out, int out_size)
{
    const float* x  = (const float*)d_in[0];
    const float* Wq = (const float*)d_in[1];
    const float* Wk = (const float*)d_in[2];
    const float* Wv = (const float*)d_in[3];
    const float* Wo = (const float*)d_in[4];
    float* out = (float*)d_out;

    float *Qp, *Kp, *Vp, *Yp, *Xr, *Wqr, *Wkr, *Wvr, *Wor;
    cudaGetSymbolAddress((void**)&Qp,  g_Q);
    cudaGetSymbolAddress((void**)&Kp,  g_K);
    cudaGetSymbolAddress((void**)&Vp,  g_V);
    cudaGetSymbolAddress((void**)&Yp,  g_Y);
    cudaGetSymbolAddress((void**)&Xr,  g_Xr);
    cudaGetSymbolAddress((void**)&Wqr, g_Wqr);
    cudaGetSymbolAddress((void**)&Wkr, g_Wkr);
    cudaGetSymbolAddress((void**)&Wvr, g_Wvr);
    cudaGetSymbolAddress((void**)&Wor, g_Wor);

    cudaFuncSetAttribute(gemm_async<true>,  cudaFuncAttributeMaxDynamicSharedMemorySize, GEMM_SMEM);
    cudaFuncSetAttribute(gemm_async<false>, cudaFuncAttributeMaxDynamicSharedMemorySize, GEMM_SMEM);
    cudaFuncSetAttribute(gemm_kv,           cudaFuncAttributeMaxDynamicSharedMemorySize, GEMM_SMEM);
    cudaFuncSetAttribute(flash_mqa_mma,     cudaFuncAttributeMaxDynamicSharedMemorySize, FL_SMEM);

    // Pre-round inputs to tf32
    round_tf32<<<(M_ * C_ / 4) / 256, 256>>>((const float4*)x,  (float4*)Xr,  M_ * C_ / 4);
    round_tf32<<<(C_ * C_ / 4) / 256, 256>>>((const float4*)Wq, (float4*)Wqr, C_ * C_ / 4);
    round_tf32<<<(C_ * DH_ / 4) / 256, 256>>>((const float4*)Wk, (float4*)Wkr, C_ * DH_ / 4);
    round_tf32<<<(C_ * DH_ / 4) / 256, 256>>>((const float4*)Wv, (float4*)Wvr, C_ * DH_ / 4);
    round_tf32<<<(C_ * C_ / 4) / 256, 256>>>((const float4*)Wo, (float4*)Wor, C_ * C_ / 4);

    // 1) Q = xr @ Wqr
    gemm_async<true><<<dim3(C_ / 128, M_ / 128), 256, GEMM_SMEM>>>(Xr, Wqr, Qp, C_, C_);
    // 2+3) K,V projections fused
    gemm_kv<<<dim3(1, M_ / 128, 2), 256, GEMM_SMEM>>>(Xr, Wkr, Wvr, Kp, Vp, DH_, C_);
    // 4) Flash MQA attention (128 queries/CTA, 128-key tiles)
    flash_mqa_mma<<<dim3(T_ / 128, H_, B_), 256, FL_SMEM>>>(Qp, Kp, Vp, Yp);
    // 5) out = Y @ Wor
    gemm_async<false><<<dim3(C_ / 128, M_ / 128), 256, GEMM_SMEM>>>(Yp, Wor, out, C_, C_);
}

// round 9
// speedup vs baseline: 1.2342x; 1.0996x over previous
#include <cuda_runtime.h>
#include <cstdint>

// Problem constants
#define B_   2
#define T_   2048
#define C_   2048
#define H_   16
#define DH_  128
#define M_   (B_ * T_)   // 4096

// Scratch (device globals — allocation-free per harness rules)
__device__ float g_Q[(size_t)M_ * C_];     // tf32-rounded
__device__ float g_K[(size_t)M_ * DH_];
__device__ float g_V[(size_t)M_ * DH_];
__device__ float g_Vt[(size_t)DH_ * M_];   // V transposed: [d][token]
__device__ float g_Y[(size_t)M_ * C_];
__device__ float g_Xr[(size_t)M_ * C_];
__device__ float g_Wqr[(size_t)C_ * C_];
__device__ float g_Wkr[(size_t)C_ * DH_];
__device__ float g_Wvr[(size_t)C_ * DH_];
__device__ float g_Wor[(size_t)C_ * C_];

__device__ __forceinline__ float tf32r(float x) {
    float y;
    asm("cvt.rna.tf32.f32 %0, %1;" : "=f"(y) : "f"(x));
    return y;
}

__device__ __forceinline__ uint32_t smem_u32(const void* p) {
    uint32_t a;
    asm("{ .reg .u64 t; cvta.to.shared.u64 t, %1; cvt.u32.u64 %0, t; }"
        : "=r"(a) : "l"(p));
    return a;
}

__device__ __forceinline__ void cp16(uint32_t dst, const void* src) {
    asm volatile("cp.async.cg.shared.global [%0], [%1], 16;" :: "r"(dst), "l"(src));
}
#define CP_COMMIT() asm volatile("cp.async.commit_group;" ::: "memory")
#define CP_WAIT(n)  asm volatile("cp.async.wait_group %0;" :: "n"(n) : "memory")

__device__ __forceinline__ void mma_tf32(float* d, const uint32_t* a, const uint32_t* b) {
    asm volatile(
        "mma.sync.aligned.m16n8k8.row.col.f32.tf32.tf32.f32 "
        "{%0,%1,%2,%3}, {%4,%5,%6,%7}, {%8,%9}, {%0,%1,%2,%3};"
        : "+f"(d[0]), "+f"(d[1]), "+f"(d[2]), "+f"(d[3])
        : "r"(a[0]), "r"(a[1]), "r"(a[2]), "r"(a[3]), "r"(b[0]), "r"(b[1]));
}

// ldmatrix: 8x8 b16 matrices; lane l gets 32-bit elem at (row l/4, col32 l%4)
__device__ __forceinline__ void ldsm_x4(uint32_t* r, uint32_t addr) {
    asm volatile("ldmatrix.sync.aligned.m8n8.x4.shared.b16 {%0,%1,%2,%3}, [%4];"
        : "=r"(r[0]), "=r"(r[1]), "=r"(r[2]), "=r"(r[3]) : "r"(addr));
}
__device__ __forceinline__ void ldsm_x2(uint32_t* r, uint32_t addr) {
    asm volatile("ldmatrix.sync.aligned.m8n8.x2.shared.b16 {%0,%1}, [%2];"
        : "=r"(r[0]), "=r"(r[1]) : "r"(addr));
}

// ---------------------------------------------------------------------------
// Fused pre-rounding of x, Wq, Wk, Wv, Wo (one launch)
// ---------------------------------------------------------------------------
#define R_N0 2097152   // x      (f4)
#define R_N1 1048576   // Wq
#define R_N2 65536     // Wk
#define R_N3 65536     // Wv
#define R_N4 1048576   // Wo
#define R_TOT (R_N0 + R_N1 + R_N2 + R_N3 + R_N4)   // 4325376 = 256*16896

__global__ __launch_bounds__(256) void round_all(
    const float4* __restrict__ x,  const float4* __restrict__ wq,
    const float4* __restrict__ wk, const float4* __restrict__ wv,
    const float4* __restrict__ wo,
    float4* __restrict__ xr,  float4* __restrict__ wqr,
    float4* __restrict__ wkr, float4* __restrict__ wvr,
    float4* __restrict__ wor)
{
    int i = blockIdx.x * 256 + threadIdx.x;
    float4 v; float4* dst;
    if (i < R_N0)                         { v = x[i];                          dst = xr  + i; }
    else if (i < R_N0 + R_N1)             { int j = i - R_N0;                  v = wq[j]; dst = wqr + j; }
    else if (i < R_N0 + R_N1 + R_N2)      { int j = i - R_N0 - R_N1;           v = wk[j]; dst = wkr + j; }
    else if (i < R_N0 + R_N1 + R_N2+R_N3) { int j = i - R_N0 - R_N1 - R_N2;    v = wv[j]; dst = wvr + j; }
    else                                  { int j = i - R_N0 - R_N1 - R_N2 - R_N3; v = wo[j]; dst = wor + j; }
    v.x = tf32r(v.x); v.y = tf32r(v.y); v.z = tf32r(v.z); v.w = tf32r(v.w);
    *dst = v;
}

// ---------------------------------------------------------------------------
// V transpose: Vt[d][token] = V[token][d]
// ---------------------------------------------------------------------------
__global__ __launch_bounds__(256) void vtrans(
    const float* __restrict__ Vin, float* __restrict__ Vt)
{
    __shared__ float t[32][33];
    int c0 = blockIdx.x * 32;   // d
    int r0 = blockIdx.y * 32;   // token
    int tx = threadIdx.x, ty = threadIdx.y;
    #pragma unroll
    for (int i = 0; i < 32; i += 8)
        t[ty + i][tx] = Vin[(size_t)(r0 + ty + i) * DH_ + c0 + tx];
    __syncthreads();
    #pragma unroll
    for (int i = 0; i < 32; i += 8)
        Vt[(size_t)(c0 + ty + i) * M_ + r0 + tx] = t[tx][ty + i];
}

// ---------------------------------------------------------------------------
// tf32 GEMM core, BK=16, 3-stage cp.async pipeline, A-frags via ldmatrix.x4.
// CTA tile 128x128, 8 warps (2x4), warp tile 64x32.
// ---------------------------------------------------------------------------
#define AS_STRIDE 20
#define BS_STRIDE 136
#define GA_ELEMS (128 * AS_STRIDE)
#define GB_ELEMS (16 * BS_STRIDE)
#define G_STAGE  (GA_ELEMS + GB_ELEMS)          // 4736 floats
#define GEMM_SMEM (3 * G_STAGE * 4)             // 56832 B

template<bool ROUND_OUT>
__device__ __forceinline__ void gemm_core(
    const float* __restrict__ A, const float* __restrict__ B,
    float* __restrict__ Cc, int Nc, int Kd, int rowBase, int colBase)
{
    extern __shared__ float gsm[];

    const int tid    = threadIdx.x;
    const int wid    = tid >> 5;
    const int lane   = tid & 31;
    const int g      = lane >> 2;
    const int tq     = lane & 3;
    const int warp_m = wid & 1;
    const int warp_n = wid >> 1;

    // ldmatrix lane offsets (A-type x4: row = l7 + lb*8, col4 = lh*4)
    const int l7 = lane & 7, lb = (lane >> 3) & 1, lh = lane >> 4;
    const uint32_t af_lane = (uint32_t)(((l7 + lb * 8) * AS_STRIDE + lh * 4) * 4);

    float acc[4][4][4];
    #pragma unroll
    for (int mi = 0; mi < 4; mi++)
        #pragma unroll
        for (int ni = 0; ni < 4; ni++)
            #pragma unroll
            for (int r = 0; r < 4; r++) acc[mi][ni][r] = 0.0f;

    const int nK = Kd >> 4;

    auto issue = [&](int kc, int s) {
        uint32_t ab = smem_u32(gsm + s * G_STAGE);
        uint32_t bb = ab + GA_ELEMS * 4;
        #pragma unroll
        for (int j = 0; j < 2; j++) {
            int op = tid + 256 * j;
            int r = op >> 2, sg = op & 3;
            cp16(ab + (uint32_t)(r * AS_STRIDE + sg * 4) * 4,
                 A + (size_t)(rowBase + r) * Kd + kc * 16 + sg * 4);
        }
        #pragma unroll
        for (int j = 0; j < 2; j++) {
            int op = tid + 256 * j;
            int r = op >> 5, sg = op & 31;
            cp16(bb + (uint32_t)(r * BS_STRIDE + sg * 4) * 4,
                 B + (size_t)(kc * 16 + r) * Nc + colBase + sg * 4);
        }
    };

    issue(0, 0); CP_COMMIT();
    issue(1, 1); CP_COMMIT();

    int s = 0;
    for (int kc = 0; kc < nK; kc++) {
        if (kc + 1 < nK) { CP_WAIT(1); } else { CP_WAIT(0); }
        __syncthreads();
        if (kc + 2 < nK) { issue(kc + 2, (kc + 2) % 3); CP_COMMIT(); }

        const float* Asf = gsm + s * G_STAGE;
        const float* Bsf = Asf + GA_ELEMS;
        const uint32_t asb = smem_u32(Asf);

        #pragma unroll
        for (int ks = 0; ks < 2; ks++) {
            uint32_t af[4][4], bf[4][2];
            #pragma unroll
            for (int mi = 0; mi < 4; mi++) {
                ldsm_x4(af[mi], asb + (uint32_t)((warp_m * 64 + mi * 16) * AS_STRIDE * 4)
                                    + (uint32_t)(ks * 32) + af_lane);
            }
            #pragma unroll
            for (int ni = 0; ni < 4; ni++) {
                int n0 = warp_n * 32 + ni * 8 + g;
                int kk = ks * 8 + tq;
                bf[ni][0] = __float_as_uint(Bsf[kk * BS_STRIDE + n0]);
                bf[ni][1] = __float_as_uint(Bsf[(kk + 4) * BS_STRIDE + n0]);
            }
            #pragma unroll
            for (int mi = 0; mi < 4; mi++)
                #pragma unroll
                for (int ni = 0; ni < 4; ni++)
                    mma_tf32(acc[mi][ni], af[mi], bf[ni]);
        }
        s = (s + 1 == 3) ? 0 : s + 1;
    }

    #pragma unroll
    for (int mi = 0; mi < 4; mi++) {
        int row = rowBase + warp_m * 64 + mi * 16 + g;
        #pragma unroll
        for (int ni = 0; ni < 4; ni++) {
            int col = colBase + warp_n * 32 + ni * 8 + tq * 2;
            float v0 = acc[mi][ni][0], v1 = acc[mi][ni][1];
            float v2 = acc[mi][ni][2], v3 = acc[mi][ni][3];
            if (ROUND_OUT) { v0 = tf32r(v0); v1 = tf32r(v1); v2 = tf32r(v2); v3 = tf32r(v3); }
            *reinterpret_cast<float2*>(&Cc[(size_t)row * Nc + col])       = make_float2(v0, v1);
            *reinterpret_cast<float2*>(&Cc[(size_t)(row + 8) * Nc + col]) = make_float2(v2, v3);
        }
    }
}

// Fused Q/K/V projections: grid (18, 32). x<16: Q col-block; 16: K; 17: V.
__global__ __launch_bounds__(256, 2) void gemm_qkv(
    const float* __restrict__ Xr,
    const float* __restrict__ Wq, const float* __restrict__ Wk, const float* __restrict__ Wv,
    float* __restrict__ Qo, float* __restrict__ Ko, float* __restrict__ Vo)
{
    const int bx = blockIdx.x, by = blockIdx.y;
    if (bx < 16)       gemm_core<true>(Xr, Wq, Qo, C_,  C_, by * 128, bx * 128);
    else if (bx == 16) gemm_core<true>(Xr, Wk, Ko, DH_, C_, by * 128, 0);
    else               gemm_core<true>(Xr, Wv, Vo, DH_, C_, by * 128, 0);
}

__global__ __launch_bounds__(256, 2) void gemm_oproj(
    const float* __restrict__ A, const float* __restrict__ B, float* __restrict__ Cc)
{
    gemm_core<false>(A, B, Cc, C_, C_, blockIdx.y * 128, blockIdx.x * 128);
}

// ---------------------------------------------------------------------------
// Tensor-core flash attention: 256 threads, 128 queries/CTA, 128-key tiles,
// ldmatrix fragments everywhere, V consumed from Vt [d][token].
// K(it+1) prefetched behind O-phase, V(it+1) behind S-phase.
// PSTR = 132: per-warp P tile is 16 rows x 128 keys (+4 pad). (R8 bug: was 36.)
// ---------------------------------------------------------------------------
#define KSTR  132
#define VTSTR 132
#define PSTR  132
#define F_OFF_V (128 * KSTR)                       // 16896
#define F_OFF_P (128 * KSTR + 128 * VTSTR)         // 33792
#define FL_SMEM ((F_OFF_P + 8 * 16 * PSTR) * 4)    // 202752 B

__global__ __launch_bounds__(256, 1) void flash_mqa_mma(
    const float* __restrict__ Q, const float* __restrict__ K,
    const float* __restrict__ Vt, float* __restrict__ Y)
{
    extern __shared__ float fsm[];
    const uint32_t sb = smem_u32(fsm);

    const int tid  = threadIdx.x;
    const int wid  = tid >> 5;
    const int lane = tid & 31;
    const int g    = lane >> 2;
    const int tq   = lane & 3;
    const int q0   = blockIdx.x * 128;
    const int h    = blockIdx.y;
    const int b    = blockIdx.z;
    const int m0   = wid * 16;
    // scale * log2(e): softmax computed in exp2 domain
    const float scale2 = 0.08838834764831845f * 1.4426950408889634f;

    // ldmatrix lane offsets
    const int l7 = lane & 7, lb = (lane >> 3) & 1, lh = lane >> 4;
    const uint32_t qf_lane = (uint32_t)(((l7 + lb * 8) * KSTR + lh * 4) * 4);   // A-type x4
    const uint32_t pf_lane = (uint32_t)(((l7 + lb * 8) * PSTR + lh * 4) * 4);   // A-type x4
    const uint32_t kf_lane = (uint32_t)((l7 * KSTR  + lb * 4) * 4);             // B-type x2
    const uint32_t vf_lane = (uint32_t)((l7 * VTSTR + lb * 4) * 4);             // B-type x2

    // ---- Stage Q (128x128) into K region, grab fragments via ldmatrix.x4
    const float* Qb = Q + ((size_t)b * T_ + q0) * C_ + h * DH_;
    #pragma unroll
    for (int j = 0; j < 16; j++) {
        int op = tid + 256 * j;
        int r = op >> 5, sg = op & 31;
        cp16(sb + (uint32_t)(r * KSTR + sg * 4) * 4, Qb + (size_t)r * C_ + sg * 4);
    }
    CP_COMMIT(); CP_WAIT(0);
    __syncthreads();

    uint32_t qf[16][4];
    {
        const uint32_t qbase = sb + (uint32_t)(m0 * KSTR * 4) + qf_lane;
        #pragma unroll
        for (int kk = 0; kk < 16; kk++) ldsm_x4(qf[kk], qbase + kk * 32);
    }
    __syncthreads();

    float oacc[16][4];
    #pragma unroll
    for (int nf = 0; nf < 16; nf++)
        #pragma unroll
        for (int r = 0; r < 4; r++) oacc[nf][r] = 0.0f;
    float mrow0 = -1e30f, mrow1 = -1e30f, lrow0 = 0.0f, lrow1 = 0.0f;

    const float* Kb  = K  + (size_t)b * T_ * DH_;
    const float* Vtb = Vt + (size_t)b * T_;   // Vt row d, col (b*T + key)
    float* Psw = fsm + F_OFF_P + wid * 16 * PSTR;
    const uint32_t psb = sb + (uint32_t)((F_OFF_P + wid * 16 * PSTR) * 4) + pf_lane;

    auto issue_K = [&](int s0t) {
        const float* Kt = Kb + (size_t)s0t * DH_;
        #pragma unroll
        for (int j = 0; j < 16; j++) {
            int op = tid + 256 * j;
            int r = op >> 5, sg = op & 31;
            cp16(sb + (uint32_t)(r * KSTR + sg * 4) * 4, Kt + (size_t)r * DH_ + sg * 4);
        }
    };
    auto issue_V = [&](int s0t) {
        const float* Vs0 = Vtb + s0t;
        #pragma unroll
        for (int j = 0; j < 16; j++) {
            int op = tid + 256 * j;
            int r = op >> 5, sg = op & 31;   // r = d row, sg = key/4
            cp16(sb + (uint32_t)(F_OFF_V + r * VTSTR + sg * 4) * 4,
                 Vs0 + (size_t)r * M_ + sg * 4);
        }
    };

    issue_K(0); CP_COMMIT();
    issue_V(0); CP_COMMIT();

    const int nTiles = T_ / 128;   // 16
    for (int it = 0; it < nTiles; it++) {
        CP_WAIT(1);
        __syncthreads();

        // ---- S = Q @ K^T (16 rows x 128 keys per warp); K-frags via ldmatrix.x2
        float sacc[16][4];
        #pragma unroll
        for (int nf = 0; nf < 16; nf++)
            #pragma unroll
            for (int r = 0; r < 4; r++) sacc[nf][r] = 0.0f;

        #pragma unroll
        for (int kk = 0; kk < 16; kk++) {
            #pragma unroll
            for (int nf = 0; nf < 16; nf++) {
                uint32_t bfr[2];
                ldsm_x2(bfr, sb + (uint32_t)(nf * 8 * KSTR * 4) + kk * 32 + kf_lane);
                mma_tf32(sacc[nf], qf[kk], bfr);
            }
        }
        #pragma unroll
        for (int nf = 0; nf < 16; nf++) {
            sacc[nf][0] *= scale2; sacc[nf][1] *= scale2;
            sacc[nf][2] *= scale2; sacc[nf][3] *= scale2;
        }

        // ---- online softmax (exp2 domain)
        float mx0 = -1e30f, mx1 = -1e30f;
        #pragma unroll
        for (int nf = 0; nf < 16; nf++) {
            mx0 = fmaxf(mx0, fmaxf(sacc[nf][0], sacc[nf][1]));
            mx1 = fmaxf(mx1, fmaxf(sacc[nf][2], sacc[nf][3]));
        }
        mx0 = fmaxf(mx0, __shfl_xor_sync(0xffffffffu, mx0, 1));
        mx0 = fmaxf(mx0, __shfl_xor_sync(0xffffffffu, mx0, 2));
        mx1 = fmaxf(mx1, __shfl_xor_sync(0xffffffffu, mx1, 1));
        mx1 = fmaxf(mx1, __shfl_xor_sync(0xffffffffu, mx1, 2));
        float mn0 = fmaxf(mrow0, mx0), mn1 = fmaxf(mrow1, mx1);
        float a0 = exp2f(mrow0 - mn0), a1 = exp2f(mrow1 - mn1);
        float rs0 = 0.0f, rs1 = 0.0f;
        #pragma unroll
        for (int nf = 0; nf < 16; nf++) {
            sacc[nf][0] = exp2f(sacc[nf][0] - mn0);
            sacc[nf][1] = exp2f(sacc[nf][1] - mn0);
            sacc[nf][2] = exp2f(sacc[nf][2] - mn1);
            sacc[nf][3] = exp2f(sacc[nf][3] - mn1);
            rs0 += sacc[nf][0] + sacc[nf][1];
            rs1 += sacc[nf][2] + sacc[nf][3];
        }
        rs0 += __shfl_xor_sync(0xffffffffu, rs0, 1);
        rs0 += __shfl_xor_sync(0xffffffffu, rs0, 2);
        rs1 += __shfl_xor_sync(0xffffffffu, rs1, 1);
        rs1 += __shfl_xor_sync(0xffffffffu, rs1, 2);
        lrow0 = lrow0 * a0 + rs0;  mrow0 = mn0;
        lrow1 = lrow1 * a1 + rs1;  mrow1 = mn1;
        #pragma unroll
        for (int nf = 0; nf < 16; nf++) {
            oacc[nf][0] *= a0; oacc[nf][1] *= a0;
            oacc[nf][2] *= a1; oacc[nf][3] *= a1;
        }
        // publish P (tf32)
        #pragma unroll
        for (int nf = 0; nf < 16; nf++) {
            *reinterpret_cast<float2*>(&Psw[g * PSTR + nf * 8 + tq * 2]) =
                make_float2(tf32r(sacc[nf][0]), tf32r(sacc[nf][1]));
            *reinterpret_cast<float2*>(&Psw[(g + 8) * PSTR + nf * 8 + tq * 2]) =
                make_float2(tf32r(sacc[nf][2]), tf32r(sacc[nf][3]));
        }

        // ---- Ks reads done -> prefetch K(it+1) behind O-phase
        __syncthreads();
        if (it + 1 < nTiles) { issue_K((it + 1) * 128); CP_COMMIT(); }

        // ---- wait V(it)
        if (it + 1 < nTiles) { CP_WAIT(1); } else { CP_WAIT(0); }
        __syncthreads();

        // ---- O += P @ V: P-frags ldmatrix.x4, V-frags ldmatrix.x2 from Vt [d][key]
        #pragma unroll
        for (int kk = 0; kk < 16; kk++) {
            uint32_t pf[4];
            ldsm_x4(pf, psb + kk * 32);
            #pragma unroll
            for (int nf = 0; nf < 16; nf++) {
                uint32_t bfr[2];
                ldsm_x2(bfr, sb + (uint32_t)((F_OFF_V + nf * 8 * VTSTR) * 4) + kk * 32 + vf_lane);
                mma_tf32(oacc[nf], pf, bfr);
            }
        }

        // ---- Vs reads done -> prefetch V(it+1) behind next S-phase
        __syncthreads();
        if (it + 1 < nTiles) { issue_V((it + 1) * 128); CP_COMMIT(); }
    }

    // ---- epilogue
    float i0 = 1.0f / lrow0, i1 = 1.0f / lrow1;
    size_t row0 = (size_t)b * T_ + q0 + m0 + g;
    size_t row1 = row0 + 8;
    #pragma unroll
    for (int nf = 0; nf < 16; nf++) {
        int col = h * DH_ + nf * 8 + tq * 2;
        *reinterpret_cast<float2*>(&Y[row0 * C_ + col]) =
            make_float2(tf32r(oacc[nf][0] * i0), tf32r(oacc[nf][1] * i0));
        *reinterpret_cast<float2*>(&Y[row1 * C_ + col]) =
            make_float2(tf32r(oacc[nf][2] * i1), tf32r(oacc[nf][3] * i1));
    }
}

// ---------------------------------------------------------------------------
// Launch
// ---------------------------------------------------------------------------
extern "C" void kernel_launch(void* const* d_in, const int* in_sizes, int n_in,
                              void* d_out, int out_size)
{
    const float* x  = (const float*)d_in[0];
    const float* Wq = (const float*)d_in[1];
    const float* Wk = (const float*)d_in[2];
    const float* Wv = (const float*)d_in[3];
    const float* Wo = (const float*)d_in[4];
    float* out = (float*)d_out;

    float *Qp, *Kp, *Vp, *Vtp, *Yp, *Xr, *Wqr, *Wkr, *Wvr, *Wor;
    cudaGetSymbolAddress((void**)&Qp,  g_Q);
    cudaGetSymbolAddress((void**)&Kp,  g_K);
    cudaGetSymbolAddress((void**)&Vp,  g_V);
    cudaGetSymbolAddress((void**)&Vtp, g_Vt);
    cudaGetSymbolAddress((void**)&Yp,  g_Y);
    cudaGetSymbolAddress((void**)&Xr,  g_Xr);
    cudaGetSymbolAddress((void**)&Wqr, g_Wqr);
    cudaGetSymbolAddress((void**)&Wkr, g_Wkr);
    cudaGetSymbolAddress((void**)&Wvr, g_Wvr);
    cudaGetSymbolAddress((void**)&Wor, g_Wor);

    cudaFuncSetAttribute(gemm_qkv,      cudaFuncAttributeMaxDynamicSharedMemorySize, GEMM_SMEM);
    cudaFuncSetAttribute(gemm_oproj,    cudaFuncAttributeMaxDynamicSharedMemorySize, GEMM_SMEM);
    cudaFuncSetAttribute(flash_mqa_mma, cudaFuncAttributeMaxDynamicSharedMemorySize, FL_SMEM);

    // 1) Pre-round all inputs (one launch)
    round_all<<<R_TOT / 256, 256>>>(
        (const float4*)x, (const float4*)Wq, (const float4*)Wk,
        (const float4*)Wv, (const float4*)Wo,
        (float4*)Xr, (float4*)Wqr, (float4*)Wkr, (float4*)Wvr, (float4*)Wor);

    // 2) Q/K/V projections fused (rounded outputs)
    gemm_qkv<<<dim3(18, M_ / 128), 256, GEMM_SMEM>>>(Xr, Wqr, Wkr, Wvr, Qp, Kp, Vp);

    // 3) Transpose V -> Vt [d][token]
    vtrans<<<dim3(DH_ / 32, M_ / 32), dim3(32, 8)>>>(Vp, Vtp);

    // 4) Flash MQA attention
    flash_mqa_mma<<<dim3(T_ / 128, H_, B_), 256, FL_SMEM>>>(Qp, Kp, Vtp, Yp);

    // 5) out = Y @ Wo
    gemm_oproj<<<dim3(C_ / 128, M_ / 128), 256, GEMM_SMEM>>>(Yp, Wor, out);
}

// round 10
// speedup vs baseline: 1.2477x; 1.0110x over previous
#include <cuda_runtime.h>
#include <cstdint>

// Problem constants
#define B_   2
#define T_   2048
#define C_   2048
#define H_   16
#define DH_  128
#define M_   (B_ * T_)   // 4096

// Scratch (device globals — allocation-free per harness rules)
__device__ float g_Q[(size_t)M_ * C_];     // tf32-rounded
__device__ float g_K[(size_t)M_ * DH_];
__device__ float g_V[(size_t)M_ * DH_];
__device__ float g_Vt[(size_t)DH_ * M_];   // V transposed: [d][token]
__device__ float g_Y[(size_t)M_ * C_];
__device__ float g_Xr[(size_t)M_ * C_];
__device__ float g_Wqr[(size_t)C_ * C_];
__device__ float g_Wkr[(size_t)C_ * DH_];
__device__ float g_Wvr[(size_t)C_ * DH_];
__device__ float g_Wor[(size_t)C_ * C_];

__device__ __forceinline__ float tf32r(float x) {
    float y;
    asm("cvt.rna.tf32.f32 %0, %1;" : "=f"(y) : "f"(x));
    return y;
}

__device__ __forceinline__ uint32_t smem_u32(const void* p) {
    uint32_t a;
    asm("{ .reg .u64 t; cvta.to.shared.u64 t, %1; cvt.u32.u64 %0, t; }"
        : "=r"(a) : "l"(p));
    return a;
}

__device__ __forceinline__ void cp16(uint32_t dst, const void* src) {
    asm volatile("cp.async.cg.shared.global [%0], [%1], 16;" :: "r"(dst), "l"(src));
}
#define CP_COMMIT() asm volatile("cp.async.commit_group;" ::: "memory")
#define CP_WAIT(n)  asm volatile("cp.async.wait_group %0;" :: "n"(n) : "memory")

__device__ __forceinline__ void mma_tf32(float* d, const uint32_t* a, const uint32_t* b) {
    asm volatile(
        "mma.sync.aligned.m16n8k8.row.col.f32.tf32.tf32.f32 "
        "{%0,%1,%2,%3}, {%4,%5,%6,%7}, {%8,%9}, {%0,%1,%2,%3};"
        : "+f"(d[0]), "+f"(d[1]), "+f"(d[2]), "+f"(d[3])
        : "r"(a[0]), "r"(a[1]), "r"(a[2]), "r"(a[3]), "r"(b[0]), "r"(b[1]));
}

__device__ __forceinline__ void ldsm_x4(uint32_t* r, uint32_t addr) {
    asm volatile("ldmatrix.sync.aligned.m8n8.x4.shared.b16 {%0,%1,%2,%3}, [%4];"
        : "=r"(r[0]), "=r"(r[1]), "=r"(r[2]), "=r"(r[3]) : "r"(addr));
}
__device__ __forceinline__ void ldsm_x2(uint32_t* r, uint32_t addr) {
    asm volatile("ldmatrix.sync.aligned.m8n8.x2.shared.b16 {%0,%1}, [%2];"
        : "=r"(r[0]), "=r"(r[1]) : "r"(addr));
}

// ---------------------------------------------------------------------------
// Fused pre-rounding of x, Wq, Wk, Wv, Wo (one launch)
// ---------------------------------------------------------------------------
#define R_N0 2097152
#define R_N1 1048576
#define R_N2 65536
#define R_N3 65536
#define R_N4 1048576
#define R_TOT (R_N0 + R_N1 + R_N2 + R_N3 + R_N4)

__global__ __launch_bounds__(256) void round_all(
    const float4* __restrict__ x,  const float4* __restrict__ wq,
    const float4* __restrict__ wk, const float4* __restrict__ wv,
    const float4* __restrict__ wo,
    float4* __restrict__ xr,  float4* __restrict__ wqr,
    float4* __restrict__ wkr, float4* __restrict__ wvr,
    float4* __restrict__ wor)
{
    int i = blockIdx.x * 256 + threadIdx.x;
    float4 v; float4* dst;
    if (i < R_N0)                         { v = x[i];                          dst = xr  + i; }
    else if (i < R_N0 + R_N1)             { int j = i - R_N0;                  v = wq[j]; dst = wqr + j; }
    else if (i < R_N0 + R_N1 + R_N2)      { int j = i - R_N0 - R_N1;           v = wk[j]; dst = wkr + j; }
    else if (i < R_N0 + R_N1 + R_N2+R_N3) { int j = i - R_N0 - R_N1 - R_N2;    v = wv[j]; dst = wvr + j; }
    else                                  { int j = i - R_N0 - R_N1 - R_N2 - R_N3; v = wo[j]; dst = wor + j; }
    v.x = tf32r(v.x); v.y = tf32r(v.y); v.z = tf32r(v.z); v.w = tf32r(v.w);
    *dst = v;
}

// ---------------------------------------------------------------------------
// V transpose: Vt[d][token] = V[token][d]
// ---------------------------------------------------------------------------
__global__ __launch_bounds__(256) void vtrans(
    const float* __restrict__ Vin, float* __restrict__ Vt)
{
    __shared__ float t[32][33];
    int c0 = blockIdx.x * 32;
    int r0 = blockIdx.y * 32;
    int tx = threadIdx.x, ty = threadIdx.y;
    #pragma unroll
    for (int i = 0; i < 32; i += 8)
        t[ty + i][tx] = Vin[(size_t)(r0 + ty + i) * DH_ + c0 + tx];
    __syncthreads();
    #pragma unroll
    for (int i = 0; i < 32; i += 8)
        Vt[(size_t)(c0 + ty + i) * M_ + r0 + tx] = t[tx][ty + i];
}

// ---------------------------------------------------------------------------
// tf32 GEMM core, BK=16, 3-stage cp.async pipeline, A-frags via ldmatrix.x4.
// ---------------------------------------------------------------------------
#define AS_STRIDE 20
#define BS_STRIDE 136
#define GA_ELEMS (128 * AS_STRIDE)
#define GB_ELEMS (16 * BS_STRIDE)
#define G_STAGE  (GA_ELEMS + GB_ELEMS)
#define GEMM_SMEM (3 * G_STAGE * 4)   // 56832 B

template<bool ROUND_OUT>
__device__ __forceinline__ void gemm_core(
    const float* __restrict__ A, const float* __restrict__ B,
    float* __restrict__ Cc, int Nc, int Kd, int rowBase, int colBase)
{
    extern __shared__ float gsm[];

    const int tid    = threadIdx.x;
    const int wid    = tid >> 5;
    const int lane   = tid & 31;
    const int g      = lane >> 2;
    const int tq     = lane & 3;
    const int warp_m = wid & 1;
    const int warp_n = wid >> 1;

    const int l7 = lane & 7, lb = (lane >> 3) & 1, lh = lane >> 4;
    const uint32_t af_lane = (uint32_t)(((l7 + lb * 8) * AS_STRIDE + lh * 4) * 4);

    float acc[4][4][4];
    #pragma unroll
    for (int mi = 0; mi < 4; mi++)
        #pragma unroll
        for (int ni = 0; ni < 4; ni++)
            #pragma unroll
            for (int r = 0; r < 4; r++) acc[mi][ni][r] = 0.0f;

    const int nK = Kd >> 4;

    auto issue = [&](int kc, int s) {
        uint32_t ab = smem_u32(gsm + s * G_STAGE);
        uint32_t bb = ab + GA_ELEMS * 4;
        #pragma unroll
        for (int j = 0; j < 2; j++) {
            int op = tid + 256 * j;
            int r = op >> 2, sg = op & 3;
            cp16(ab + (uint32_t)(r * AS_STRIDE + sg * 4) * 4,
                 A + (size_t)(rowBase + r) * Kd + kc * 16 + sg * 4);
        }
        #pragma unroll
        for (int j = 0; j < 2; j++) {
            int op = tid + 256 * j;
            int r = op >> 5, sg = op & 31;
            cp16(bb + (uint32_t)(r * BS_STRIDE + sg * 4) * 4,
                 B + (size_t)(kc * 16 + r) * Nc + colBase + sg * 4);
        }
    };

    issue(0, 0); CP_COMMIT();
    issue(1, 1); CP_COMMIT();

    int s = 0;
    for (int kc = 0; kc < nK; kc++) {
        if (kc + 1 < nK) { CP_WAIT(1); } else { CP_WAIT(0); }
        __syncthreads();
        if (kc + 2 < nK) { issue(kc + 2, (kc + 2) % 3); CP_COMMIT(); }

        const float* Asf = gsm + s * G_STAGE;
        const float* Bsf = Asf + GA_ELEMS;
        const uint32_t asb = smem_u32(Asf);

        #pragma unroll
        for (int ks = 0; ks < 2; ks++) {
            uint32_t af[4][4], bf[4][2];
            #pragma unroll
            for (int mi = 0; mi < 4; mi++) {
                ldsm_x4(af[mi], asb + (uint32_t)((warp_m * 64 + mi * 16) * AS_STRIDE * 4)
                                    + (uint32_t)(ks * 32) + af_lane);
            }
            #pragma unroll
            for (int ni = 0; ni < 4; ni++) {
                int n0 = warp_n * 32 + ni * 8 + g;
                int kk = ks * 8 + tq;
                bf[ni][0] = __float_as_uint(Bsf[kk * BS_STRIDE + n0]);
                bf[ni][1] = __float_as_uint(Bsf[(kk + 4) * BS_STRIDE + n0]);
            }
            #pragma unroll
            for (int mi = 0; mi < 4; mi++)
                #pragma unroll
                for (int ni = 0; ni < 4; ni++)
                    mma_tf32(acc[mi][ni], af[mi], bf[ni]);
        }
        s = (s + 1 == 3) ? 0 : s + 1;
    }

    #pragma unroll
    for (int mi = 0; mi < 4; mi++) {
        int row = rowBase + warp_m * 64 + mi * 16 + g;
        #pragma unroll
        for (int ni = 0; ni < 4; ni++) {
            int col = colBase + warp_n * 32 + ni * 8 + tq * 2;
            float v0 = acc[mi][ni][0], v1 = acc[mi][ni][1];
            float v2 = acc[mi][ni][2], v3 = acc[mi][ni][3];
            if (ROUND_OUT) { v0 = tf32r(v0); v1 = tf32r(v1); v2 = tf32r(v2); v3 = tf32r(v3); }
            *reinterpret_cast<float2*>(&Cc[(size_t)row * Nc + col])       = make_float2(v0, v1);
            *reinterpret_cast<float2*>(&Cc[(size_t)(row + 8) * Nc + col]) = make_float2(v2, v3);
        }
    }
}

__global__ __launch_bounds__(256, 2) void gemm_qkv(
    const float* __restrict__ Xr,
    const float* __restrict__ Wq, const float* __restrict__ Wk, const float* __restrict__ Wv,
    float* __restrict__ Qo, float* __restrict__ Ko, float* __restrict__ Vo)
{
    const int bx = blockIdx.x, by = blockIdx.y;
    if (bx < 16)       gemm_core<true>(Xr, Wq, Qo, C_,  C_, by * 128, bx * 128);
    else if (bx == 16) gemm_core<true>(Xr, Wk, Ko, DH_, C_, by * 128, 0);
    else               gemm_core<true>(Xr, Wv, Vo, DH_, C_, by * 128, 0);
}

__global__ __launch_bounds__(256, 2) void gemm_oproj(
    const float* __restrict__ A, const float* __restrict__ B, float* __restrict__ Cc)
{
    gemm_core<false>(A, B, Cc, C_, C_, blockIdx.y * 128, blockIdx.x * 128);
}

// ---------------------------------------------------------------------------
// Tensor-core flash attention: 256 threads, 128 queries/CTA, 64-key tiles,
// K and V DOUBLE-BUFFERED (one combined commit group per tile), only TWO
// __syncthreads per tile — warps skew freely through S/softmax/O so MUFU
// (softmax) of one warp overlaps HMMA of another on the same SMSP.
// ---------------------------------------------------------------------------
#define KSTR   132
#define V64STR 68
#define PSTR   68
#define OFF_K(s)  ((s) * 64 * KSTR)              // 0, 8448
#define OFF_V(s)  (16896 + (s) * 128 * V64STR)   // 16896, 25600
#define OFF_P     (16896 + 2 * 128 * V64STR)     // 34304
#define FL_SMEM   ((OFF_P + 8 * 16 * PSTR) * 4)  // 172032 B

__global__ __launch_bounds__(256, 1) void flash_mqa_mma(
    const float* __restrict__ Q, const float* __restrict__ K,
    const float* __restrict__ Vt, float* __restrict__ Y)
{
    extern __shared__ float fsm[];
    const uint32_t sb = smem_u32(fsm);

    const int tid  = threadIdx.x;
    const int wid  = tid >> 5;
    const int lane = tid & 31;
    const int g    = lane >> 2;
    const int tq   = lane & 3;
    const int q0   = blockIdx.x * 128;
    const int h    = blockIdx.y;
    const int b    = blockIdx.z;
    const int m0   = wid * 16;
    const float scale2 = 0.08838834764831845f * 1.4426950408889634f;  // scale*log2e

    const int l7 = lane & 7, lb = (lane >> 3) & 1, lh = lane >> 4;
    const uint32_t qf_lane = (uint32_t)(((l7 + lb * 8) * KSTR   + lh * 4) * 4);
    const uint32_t pf_lane = (uint32_t)(((l7 + lb * 8) * PSTR   + lh * 4) * 4);
    const uint32_t kf_lane = (uint32_t)((l7 * KSTR   + lb * 4) * 4);
    const uint32_t vf_lane = (uint32_t)((l7 * V64STR + lb * 4) * 4);

    // ---- Stage Q (128x128, stride KSTR) at smem offset 0 (aliases K/V bufs)
    const float* Qb = Q + ((size_t)b * T_ + q0) * C_ + h * DH_;
    #pragma unroll
    for (int j = 0; j < 16; j++) {
        int op = tid + 256 * j;
        int r = op >> 5, sg = op & 31;
        cp16(sb + (uint32_t)(r * KSTR + sg * 4) * 4, Qb + (size_t)r * C_ + sg * 4);
    }
    CP_COMMIT(); CP_WAIT(0);
    __syncthreads();

    uint32_t qf[16][4];
    {
        const uint32_t qbase = sb + (uint32_t)(m0 * KSTR * 4) + qf_lane;
        #pragma unroll
        for (int kk = 0; kk < 16; kk++) ldsm_x4(qf[kk], qbase + kk * 32);
    }
    __syncthreads();

    float oacc[16][4];
    #pragma unroll
    for (int nf = 0; nf < 16; nf++)
        #pragma unroll
        for (int r = 0; r < 4; r++) oacc[nf][r] = 0.0f;
    float mrow0 = -1e30f, mrow1 = -1e30f, lrow0 = 0.0f, lrow1 = 0.0f;

    const float* Kb  = K  + (size_t)b * T_ * DH_;
    const float* Vtb = Vt + (size_t)b * T_;
    float* Psw = fsm + OFF_P + wid * 16 * PSTR;
    const uint32_t psb = sb + (uint32_t)((OFF_P + wid * 16 * PSTR) * 4) + pf_lane;

    // combined K+V tile loader (one commit group): K 64x128, V 128x64 (from Vt)
    auto issue_KV = [&](int s0t, int s) {
        const float* Kt  = Kb  + (size_t)s0t * DH_;
        const float* Vs0 = Vtb + s0t;
        #pragma unroll
        for (int j = 0; j < 8; j++) {
            int op = tid + 256 * j;        // 0..2047
            int r = op >> 5, sg = op & 31; // K: 64 rows x 32 f4
            cp16(sb + (uint32_t)(OFF_K(s) + r * KSTR + sg * 4) * 4,
                 Kt + (size_t)r * DH_ + sg * 4);
        }
        #pragma unroll
        for (int j = 0; j < 8; j++) {
            int op = tid + 256 * j;        // V: 128 d-rows x 16 f4
            int r = op >> 4, sg = op & 15;
            cp16(sb + (uint32_t)(OFF_V(s) + r * V64STR + sg * 4) * 4,
                 Vs0 + (size_t)r * M_ + sg * 4);
        }
    };

    issue_KV(0, 0); CP_COMMIT();

    const int nTiles = T_ / 64;   // 32
    for (int it = 0; it < nTiles; it++) {
        const int s = it & 1;
        if (it + 1 < nTiles) {
            issue_KV((it + 1) * 64, s ^ 1);   // buf s^1 free since tile it-1 retired
            CP_COMMIT();
            CP_WAIT(1);                        // tile it resident
        } else {
            CP_WAIT(0);
        }
        __syncthreads();   // (1) all warps see buf s full

        // ---- S = Q @ K^T  (16 rows x 64 keys per warp)
        float sacc[8][4];
        #pragma unroll
        for (int nf = 0; nf < 8; nf++)
            #pragma unroll
            for (int r = 0; r < 4; r++) sacc[nf][r] = 0.0f;

        #pragma unroll
        for (int kk = 0; kk < 16; kk++) {
            #pragma unroll
            for (int nf = 0; nf < 8; nf++) {
                uint32_t bfr[2];
                ldsm_x2(bfr, sb + (uint32_t)((OFF_K(s) + nf * 8 * KSTR) * 4) + kk * 32 + kf_lane);
                mma_tf32(sacc[nf], qf[kk], bfr);
            }
        }
        #pragma unroll
        for (int nf = 0; nf < 8; nf++) {
            sacc[nf][0] *= scale2; sacc[nf][1] *= scale2;
            sacc[nf][2] *= scale2; sacc[nf][3] *= scale2;
        }

        // ---- online softmax (exp2 domain), warp-private
        float mx0 = -1e30f, mx1 = -1e30f;
        #pragma unroll
        for (int nf = 0; nf < 8; nf++) {
            mx0 = fmaxf(mx0, fmaxf(sacc[nf][0], sacc[nf][1]));
            mx1 = fmaxf(mx1, fmaxf(sacc[nf][2], sacc[nf][3]));
        }
        mx0 = fmaxf(mx0, __shfl_xor_sync(0xffffffffu, mx0, 1));
        mx0 = fmaxf(mx0, __shfl_xor_sync(0xffffffffu, mx0, 2));
        mx1 = fmaxf(mx1, __shfl_xor_sync(0xffffffffu, mx1, 1));
        mx1 = fmaxf(mx1, __shfl_xor_sync(0xffffffffu, mx1, 2));
        float mn0 = fmaxf(mrow0, mx0), mn1 = fmaxf(mrow1, mx1);
        float a0 = exp2f(mrow0 - mn0), a1 = exp2f(mrow1 - mn1);
        float rs0 = 0.0f, rs1 = 0.0f;
        #pragma unroll
        for (int nf = 0; nf < 8; nf++) {
            sacc[nf][0] = exp2f(sacc[nf][0] - mn0);
            sacc[nf][1] = exp2f(sacc[nf][1] - mn0);
            sacc[nf][2] = exp2f(sacc[nf][2] - mn1);
            sacc[nf][3] = exp2f(sacc[nf][3] - mn1);
            rs0 += sacc[nf][0] + sacc[nf][1];
            rs1 += sacc[nf][2] + sacc[nf][3];
        }
        rs0 += __shfl_xor_sync(0xffffffffu, rs0, 1);
        rs0 += __shfl_xor_sync(0xffffffffu, rs0, 2);
        rs1 += __shfl_xor_sync(0xffffffffu, rs1, 1);
        rs1 += __shfl_xor_sync(0xffffffffu, rs1, 2);
        lrow0 = lrow0 * a0 + rs0;  mrow0 = mn0;
        lrow1 = lrow1 * a1 + rs1;  mrow1 = mn1;
        #pragma unroll
        for (int nf = 0; nf < 16; nf++) {
            oacc[nf][0] *= a0; oacc[nf][1] *= a0;
            oacc[nf][2] *= a1; oacc[nf][3] *= a1;
        }

        // publish P (tf32) — warp-private buffer, warp-level sync only
        #pragma unroll
        for (int nf = 0; nf < 8; nf++) {
            *reinterpret_cast<float2*>(&Psw[g * PSTR + nf * 8 + tq * 2]) =
                make_float2(tf32r(sacc[nf][0]), tf32r(sacc[nf][1]));
            *reinterpret_cast<float2*>(&Psw[(g + 8) * PSTR + nf * 8 + tq * 2]) =
                make_float2(tf32r(sacc[nf][2]), tf32r(sacc[nf][3]));
        }
        __syncwarp();

        // ---- O += P @ V  (k = 64 keys; V-frags from Vt tile [d][key])
        #pragma unroll
        for (int kk = 0; kk < 8; kk++) {
            uint32_t pf[4];
            ldsm_x4(pf, psb + kk * 32);
            #pragma unroll
            for (int nf = 0; nf < 16; nf++) {
                uint32_t bfr[2];
                ldsm_x2(bfr, sb + (uint32_t)((OFF_V(s) + nf * 8 * V64STR) * 4) + kk * 32 + vf_lane);
                mma_tf32(oacc[nf], pf, bfr);
            }
        }
        __syncthreads();   // (2) all warps done with buf s — next iter may overwrite
    }

    // ---- epilogue: normalize, round (feeds O-proj), write Y
    float i0 = 1.0f / lrow0, i1 = 1.0f / lrow1;
    size_t row0 = (size_t)b * T_ + q0 + m0 + g;
    size_t row1 = row0 + 8;
    #pragma unroll
    for (int nf = 0; nf < 16; nf++) {
        int col = h * DH_ + nf * 8 + tq * 2;
        *reinterpret_cast<float2*>(&Y[row0 * C_ + col]) =
            make_float2(tf32r(oacc[nf][0] * i0), tf32r(oacc[nf][1] * i0));
        *reinterpret_cast<float2*>(&Y[row1 * C_ + col]) =
            make_float2(tf32r(oacc[nf][2] * i1), tf32r(oacc[nf][3] * i1));
    }
}

// ---------------------------------------------------------------------------
// Launch
// ---------------------------------------------------------------------------
extern "C" void kernel_launch(void* const* d_in, const int* in_sizes, int n_in,
                              void* d_out, int out_size)
{
    const float* x  = (const float*)d_in[0];
    const float* Wq = (const float*)d_in[1];
    const float* Wk = (const float*)d_in[2];
    const float* Wv = (const float*)d_in[3];
    const float* Wo = (const float*)d_in[4];
    float* out = (float*)d_out;

    float *Qp, *Kp, *Vp, *Vtp, *Yp, *Xr, *Wqr, *Wkr, *Wvr, *Wor;
    cudaGetSymbolAddress((void**)&Qp,  g_Q);
    cudaGetSymbolAddress((void**)&Kp,  g_K);
    cudaGetSymbolAddress((void**)&Vp,  g_V);
    cudaGetSymbolAddress((void**)&Vtp, g_Vt);
    cudaGetSymbolAddress((void**)&Yp,  g_Y);
    cudaGetSymbolAddress((void**)&Xr,  g_Xr);
    cudaGetSymbolAddress((void**)&Wqr, g_Wqr);
    cudaGetSymbolAddress((void**)&Wkr, g_Wkr);
    cudaGetSymbolAddress((void**)&Wvr, g_Wvr);
    cudaGetSymbolAddress((void**)&Wor, g_Wor);

    cudaFuncSetAttribute(gemm_qkv,      cudaFuncAttributeMaxDynamicSharedMemorySize, GEMM_SMEM);
    cudaFuncSetAttribute(gemm_oproj,    cudaFuncAttributeMaxDynamicSharedMemorySize, GEMM_SMEM);
    cudaFuncSetAttribute(flash_mqa_mma, cudaFuncAttributeMaxDynamicSharedMemorySize, FL_SMEM);

    // 1) Pre-round all inputs
    round_all<<<R_TOT / 256, 256>>>(
        (const float4*)x, (const float4*)Wq, (const float4*)Wk,
        (const float4*)Wv, (const float4*)Wo,
        (float4*)Xr, (float4*)Wqr, (float4*)Wkr, (float4*)Wvr, (float4*)Wor);

    // 2) Q/K/V projections fused
    gemm_qkv<<<dim3(18, M_ / 128), 256, GEMM_SMEM>>>(Xr, Wqr, Wkr, Wvr, Qp, Kp, Vp);

    // 3) Transpose V -> Vt
    vtrans<<<dim3(DH_ / 32, M_ / 32), dim3(32, 8)>>>(Vp, Vtp);

    // 4) Flash MQA attention (desynchronized warps, 2 syncs/tile)
    flash_mqa_mma<<<dim3(T_ / 128, H_, B_), 256, FL_SMEM>>>(Qp, Kp, Vtp, Yp);

    // 5) out = Y @ Wo
    gemm_oproj<<<dim3(C_ / 128, M_ / 128), 256, GEMM_SMEM>>>(Yp, Wor, out);
}